// round 3
// baseline (speedup 1.0000x reference)
#include <cuda_runtime.h>

#define NTIME   4096
#define NBATCH  4096
#define NEXTRA  256
#define COLS    8                 // batch columns per CTA
#define STRIDE  4100              // padded column stride in words (4100 % 32 == 4)
#define THREADS 512
#define OPT     ((NEXTRA * COLS) / THREADS)   // outputs per thread = 4

__global__ __launch_bounds__(THREADS, 1)
void interp_kernel(const float* __restrict__ times,
                   const float* __restrict__ values,
                   const float* __restrict__ t,
                   float* __restrict__ out)
{
    extern __shared__ float s_times[];   // [COLS][STRIDE], column-major per c

    const int b0  = blockIdx.x * COLS;
    const int tid = threadIdx.x;

    // ---- Stage times[:, b0:b0+COLS] into SMEM, coalesced float4 row loads ----
    // Element e covers (row i, half c4): c4 in {0,1}, columns c4*4 .. c4*4+3.
    const float4* tg = reinterpret_cast<const float4*>(times + b0);
    #pragma unroll 4
    for (int e = tid; e < NTIME * (COLS / 4); e += THREADS) {
        int i  = e >> 1;       // COLS/4 == 2
        int c4 = e & 1;
        float4 v = tg[i * (NBATCH / 4) + c4];
        int cb = c4 * 4;
        s_times[(cb + 0) * STRIDE + i] = v.x;
        s_times[(cb + 1) * STRIDE + i] = v.y;
        s_times[(cb + 2) * STRIDE + i] = v.z;
        s_times[(cb + 3) * STRIDE + i] = v.w;
    }
    __syncthreads();

    // ---- 4 outputs per thread, interleaved for ILP ----
    // THREADS % COLS == 0 -> all 4 outputs of a thread share the same column.
    const int    c    = tid & (COLS - 1);
    const int    qb   = tid >> 3;                 // base query row; +64 per k
    const float* sc   = s_times + c * STRIDE;     // shared column base
    const float* vcol = values + b0 + c;          // gmem values column base

    int   oidx[OPT];
    float tq[OPT];
    int   cnt[OPT];

    #pragma unroll
    for (int k = 0; k < OPT; k++) {
        int q   = qb + k * (THREADS / COLS);
        oidx[k] = q * NBATCH + b0 + c;            // coalesced t load / out store
        tq[k]   = t[oidx[k]];
        cnt[k]  = 0;
    }

    // ---- Power-of-two branchless upper-bound: cnt = #(times <= tq) ----
    #pragma unroll
    for (int step = NTIME / 2; step >= 1; step >>= 1) {
        #pragma unroll
        for (int k = 0; k < OPT; k++) {
            int np = cnt[k] + step;
            if (sc[np - 1] <= tq[k]) cnt[k] = np;
        }
    }

    // ---- Interpolate ----
    #pragma unroll
    for (int k = 0; k < OPT; k++) {
        int count = cnt[k];
        int gi    = (count == NTIME) ? 0 : count;          // count % NTIME
        int sidx  = (gi == 0) ? (NTIME - 2) : (gi - 1);    // slope index (len NTIME-1)
        // idx for t0/v0: gi==0 -> NTIME-1 == sidx+1, else gi-1 == sidx
        float tlo = sc[sidx];
        float thi = sc[sidx + 1];

        float vlo = __ldg(vcol + (size_t)sidx * NBATCH);
        float vhi = __ldg(vcol + (size_t)(sidx + 1) * NBATCH);

        float t0 = (gi == 0) ? thi : tlo;
        float v0 = (gi == 0) ? vhi : vlo;
        float s0 = (vhi - vlo) / (thi - tlo);
        out[oidx[k]] = v0 + s0 * (tq[k] - t0);
    }
}

extern "C" void kernel_launch(void* const* d_in, const int* in_sizes, int n_in,
                              void* d_out, int out_size)
{
    const float* times  = (const float*)d_in[0];
    const float* values = (const float*)d_in[1];
    const float* t      = (const float*)d_in[2];
    float*       out    = (float*)d_out;

    size_t smem = (size_t)COLS * STRIDE * sizeof(float);   // 131,200 B
    cudaFuncSetAttribute(interp_kernel,
                         cudaFuncAttributeMaxDynamicSharedMemorySize, (int)smem);
    interp_kernel<<<NBATCH / COLS, THREADS, smem>>>(times, values, t, out);
}